// round 3
// baseline (speedup 1.0000x reference)
#include <cuda_runtime.h>
#include <math.h>
#include <stdint.h>
#include <stddef.h>

// Problem constants
#define Bv   1024
#define Tv   256
#define EH   256
#define DH   512
#define ZL   128
#define PTc  5
#define OUTC 123
#define NBLK 148
#define NTHR 256

// ---------------- device scratch (static, no allocation) ----------------
__device__ float d_WhhF[4*EH*EH];     // encoder fwd recurrent, gate-interleaved [1024][256]
__device__ float d_WihF[4*EH*PTc];    // encoder fwd input, interleaved [1024][5]
__device__ float d_bF[4*EH];          // encoder fwd bias, interleaved
__device__ float d_WhhD[4*DH*DH];     // decoder recurrent, interleaved [2048][512]
__device__ float d_WihS[4*DH*PTc];    // decoder stroke-input, interleaved [2048][5]
__device__ float d_hE[2][Bv*EH];      // encoder h double buffer
__device__ float d_cE[Bv*EH];
__device__ float d_hback[Bv*EH];      // backward-dir h (single step)
__device__ float d_z[Bv*ZL];
__device__ float d_hD[2][Bv*DH];      // decoder h double buffer
__device__ float d_cD[Bv*DH];
__device__ float d_zproj[Bv*4*DH];    // z @ Wih_z^T + b  (interleaved) [1024][2048]
__device__ float d_qpart[Tv*16];      // deterministic per-(step, row-tile) exp_qk partial sums
__device__ unsigned g_count;
__device__ volatile unsigned g_gen;

// ---------------- helpers ----------------
__device__ __forceinline__ float sigf(float x) { return 1.f / (1.f + __expf(-x)); }
__device__ __forceinline__ float tanh_f(float x) {
    float ax = fabsf(x);
    float e = __expf(2.f * ax);
    float t = 1.f - 2.f / (e + 1.f);   // e=inf -> t=1
    return copysignf(t, x);
}
__device__ __forceinline__ float wsum32(float v) {
    #pragma unroll
    for (int o = 16; o; o >>= 1) v += __shfl_xor_sync(0xffffffffu, v, o);
    return v;
}
__device__ __forceinline__ float wmax32(float v) {
    #pragma unroll
    for (int o = 16; o; o >>= 1) v = fmaxf(v, __shfl_xor_sync(0xffffffffu, v, o));
    return v;
}

// software grid barrier (all NBLK blocks co-resident: 1 block/SM, 148 <= 152 SMs)
__device__ __forceinline__ void grid_sync() {
    __threadfence();
    __syncthreads();
    if (threadIdx.x == 0) {
        unsigned gen = g_gen;
        if (atomicAdd(&g_count, 1u) == NBLK - 1) {
            g_count = 0;
            __threadfence();
            g_gen = gen + 1;
        } else {
            while (g_gen == gen) { __nanosleep(128); }
        }
    }
    __syncthreads();
    __threadfence();
}

// ---------------- fused gate GEMM + LSTM cell update ----------------
// Tile: 64 rows x 128 cols (= 32 hidden units x 4 gates). 256 threads, 4x8 per thread.
// out[b][n] = init(b,n) + x(b,:) @ Wih5[n,:]^T + hprev(b,:) @ W[n,:]^T, then cell update.
__device__ __forceinline__ void gate_tile_impl(
    const float* __restrict__ hprev,   // [Bv][K]   (K == H)
    const float* __restrict__ W,       // [4H][K]   interleaved
    const float* __restrict__ Wih5,    // [4H][5]   interleaved
    const float* __restrict__ zproj,   // [Bv][4H]  or nullptr (then bias used)
    const float* __restrict__ bias,    // [4H]      interleaved
    const float* __restrict__ s, int xt,   // xt < 0 -> s0 = (0,0,1,0,0)
    float* __restrict__ cbuf, float* __restrict__ hnext,  // [Bv][H]
    int row0, int col0, int K, int H,
    float (*As)[68], float (*Bs)[132])
{
    const int tid = threadIdx.x;
    const int tx = tid & 15, ty = tid >> 4;
    const int N4 = 4 * H;

    int ncol[8];
    #pragma unroll
    for (int j = 0; j < 8; j++) ncol[j] = col0 + ((j >> 2) << 6) + tx * 4 + (j & 3);

    float xr[4][5];
    #pragma unroll
    for (int i = 0; i < 4; i++) {
        int row = row0 + ty * 4 + i;
        if (xt < 0) {
            xr[i][0] = 0.f; xr[i][1] = 0.f; xr[i][2] = 1.f; xr[i][3] = 0.f; xr[i][4] = 0.f;
        } else {
            const float* xp = s + ((size_t)row * Tv + xt) * PTc;
            #pragma unroll
            for (int k = 0; k < 5; k++) xr[i][k] = xp[k];
        }
    }

    float acc[4][8];
    if (zproj) {
        #pragma unroll
        for (int i = 0; i < 4; i++) {
            const float* zp = zproj + (size_t)(row0 + ty * 4 + i) * N4;
            #pragma unroll
            for (int j = 0; j < 8; j++) acc[i][j] = zp[ncol[j]];
        }
    } else {
        #pragma unroll
        for (int j = 0; j < 8; j++) {
            float bi = bias[ncol[j]];
            #pragma unroll
            for (int i = 0; i < 4; i++) acc[i][j] = bi;
        }
    }
    #pragma unroll
    for (int j = 0; j < 8; j++) {
        #pragma unroll
        for (int k = 0; k < 5; k++) {
            float w = Wih5[ncol[j] * 5 + k];
            #pragma unroll
            for (int i = 0; i < 4; i++) acc[i][j] += xr[i][k] * w;
        }
    }

    for (int kb = 0; kb < K; kb += 16) {
        #pragma unroll
        for (int l = 0; l < 4; l++) {
            int idx = tid + l * 256;
            int r = idx >> 4, kk = idx & 15;
            As[kk][r] = hprev[(size_t)(row0 + r) * K + kb + kk];
        }
        #pragma unroll
        for (int l = 0; l < 8; l++) {
            int idx = tid + l * 256;
            int n = idx >> 4, kk = idx & 15;
            Bs[kk][n] = W[(size_t)(col0 + n) * K + kb + kk];
        }
        __syncthreads();
        #pragma unroll
        for (int kk = 0; kk < 16; kk++) {
            float a[4], bv[8];
            #pragma unroll
            for (int i = 0; i < 4; i++) a[i] = As[kk][ty * 4 + i];
            #pragma unroll
            for (int j = 0; j < 8; j++) bv[j] = Bs[kk][((j >> 2) << 6) + tx * 4 + (j & 3)];
            #pragma unroll
            for (int i = 0; i < 4; i++)
                #pragma unroll
                for (int j = 0; j < 8; j++) acc[i][j] += a[i] * bv[j];
        }
        __syncthreads();
    }

    // fused LSTM cell update: each thread owns 2 complete units x 4 rows
    #pragma unroll
    for (int i = 0; i < 4; i++) {
        int row = row0 + ty * 4 + i;
        #pragma unroll
        for (int jj = 0; jj < 2; jj++) {
            int u = (col0 + jj * 64 + tx * 4) >> 2;
            float gi = acc[i][jj * 4 + 0];
            float gf = acc[i][jj * 4 + 1];
            float gg = acc[i][jj * 4 + 2];
            float go = acc[i][jj * 4 + 3];
            size_t p = (size_t)row * H + u;
            float c = sigf(gf) * cbuf[p] + sigf(gi) * tanh_f(gg);
            cbuf[p] = c;
            hnext[p] = sigf(go) * tanh_f(c);
        }
    }
}

// ---------------- y projection + mixture transforms for one 64-row tile ----------------
__device__ __forceinline__ void y_tile(
    const float* __restrict__ hcur, const float* __restrict__ Wout,
    const float* __restrict__ bout, float* __restrict__ out,
    int tstep, int row0,
    float (*As)[68], float (*Bs)[132], float (*ys)[124], float* wsum)
{
    const int tid = threadIdx.x;
    const int tx = tid & 15, ty = tid >> 4;

    float acc[4][8];
    #pragma unroll
    for (int j = 0; j < 8; j++) {
        int n = tx * 8 + j;
        float bi = (n < OUTC) ? bout[n] : 0.f;
        #pragma unroll
        for (int i = 0; i < 4; i++) acc[i][j] = bi;
    }

    for (int kb = 0; kb < DH; kb += 16) {
        #pragma unroll
        for (int l = 0; l < 4; l++) {
            int idx = tid + l * 256;
            int r = idx >> 4, kk = idx & 15;
            As[kk][r] = hcur[(size_t)(row0 + r) * DH + kb + kk];
        }
        #pragma unroll
        for (int l = 0; l < 8; l++) {
            int idx = tid + l * 256;
            int n = idx >> 4, kk = idx & 15;
            Bs[kk][n] = (n < OUTC) ? Wout[(size_t)n * DH + kb + kk] : 0.f;
        }
        __syncthreads();
        #pragma unroll
        for (int kk = 0; kk < 16; kk++) {
            float a[4], bv[8];
            #pragma unroll
            for (int i = 0; i < 4; i++) a[i] = As[kk][ty * 4 + i];
            #pragma unroll
            for (int j = 0; j < 8; j++) bv[j] = Bs[kk][tx * 8 + j];
            #pragma unroll
            for (int i = 0; i < 4; i++)
                #pragma unroll
                for (int j = 0; j < 8; j++) acc[i][j] += a[i] * bv[j];
        }
        __syncthreads();
    }

    #pragma unroll
    for (int i = 0; i < 4; i++)
        #pragma unroll
        for (int j = 0; j < 8; j++) {
            int n = tx * 8 + j;
            if (n < OUTC) ys[ty * 4 + i][n] = acc[i][j];
        }
    __syncthreads();

    // mixture transforms: 8 warps x 8 rows
    int w = tid >> 5, lane = tid & 31;
    float qacc = 0.f;
    for (int rr = 0; rr < 8; rr++) {
        int r = w * 8 + rr;
        int brow = row0 + r;
        float* orow = out + ((size_t)tstep * Bv + brow) * OUTC;
        float v = (lane < 20) ? ys[r][lane * 6] : -3.0e38f;
        float m = wmax32(v);
        float e = (lane < 20) ? __expf(v - m) : 0.f;
        float ss = wsum32(e);
        if (lane < 20) {
            orow[lane]        = e / ss;
            orow[20 + lane]   = ys[r][lane * 6 + 1];
            orow[40 + lane]   = ys[r][lane * 6 + 2];
            orow[60 + lane]   = __expf(ys[r][lane * 6 + 3]);
            orow[80 + lane]   = __expf(ys[r][lane * 6 + 4]);
            orow[100 + lane]  = tanh_f(ys[r][lane * 6 + 5]);
        } else if (lane < 23) {
            float eq = __expf(ys[r][120 + lane - 20]);
            orow[120 + lane - 20] = eq;   // normalized later by qknorm
            qacc += eq;
        }
    }
    float qs = wsum32(qacc);
    if (lane == 0) wsum[w] = qs;
    __syncthreads();
    if (tid == 0) {
        float tot = 0.f;
        #pragma unroll
        for (int i = 0; i < 8; i++) tot += wsum[i];
        d_qpart[tstep * 16 + (row0 >> 6)] = tot;
    }
    __syncthreads();
}

__device__ __forceinline__ void qknorm(float* __restrict__ out, int t) {
    float tot = 0.f;
    #pragma unroll
    for (int i = 0; i < 16; i++) tot += d_qpart[t * 16 + i];
    float inv = 1.f / tot;
    for (int idx = blockIdx.x * NTHR + threadIdx.x; idx < Bv * 3; idx += NBLK * NTHR)
        out[((size_t)t * Bv + (idx / 3)) * OUTC + 120 + (idx % 3)] *= inv;
}

// ---------------- kernels ----------------
__global__ void reset_k() { g_count = 0; g_gen = 0; }

__global__ void prep_k(const float* __restrict__ eWihF, const float* __restrict__ eWhhF,
                       const float* __restrict__ ebF,  const float* __restrict__ eWihB,
                       const float* __restrict__ ebB,  const float* __restrict__ dWih,
                       const float* __restrict__ dWhh, const float* __restrict__ s)
{
    int gt = blockIdx.x * blockDim.x + threadIdx.x;
    int gs = gridDim.x * blockDim.x;
    for (int i = gt; i < 4 * DH * DH; i += gs) {
        int n = i / DH, k = i - n * DH, j = n >> 2, g4 = n & 3;
        d_WhhD[i] = dWhh[(size_t)(g4 * DH + j) * DH + k];
    }
    for (int i = gt; i < 4 * DH * PTc; i += gs) {
        int n = i / PTc, k = i - n * PTc, j = n >> 2, g4 = n & 3;
        d_WihS[i] = dWih[(size_t)(g4 * DH + j) * (PTc + ZL) + k];
    }
    for (int i = gt; i < 4 * EH * EH; i += gs) {
        int n = i / EH, k = i - n * EH, j = n >> 2, g4 = n & 3;
        d_WhhF[i] = eWhhF[(size_t)(g4 * EH + j) * EH + k];
    }
    for (int i = gt; i < 4 * EH * PTc; i += gs) {
        int n = i / PTc, k = i - n * PTc, j = n >> 2, g4 = n & 3;
        d_WihF[i] = eWihF[(g4 * EH + j) * PTc + k];
    }
    for (int i = gt; i < 4 * EH; i += gs) {
        int j = i >> 2, g4 = i & 3;
        d_bF[i] = ebF[g4 * EH + j];
    }
    for (int i = gt; i < Bv * EH; i += gs) { d_hE[0][i] = 0.f; d_cE[i] = 0.f; }
    // backward-direction LSTM: only one step (zero state, input x[:, T-1])
    for (int i = gt; i < Bv * EH; i += gs) {
        int b = i / EH, j = i - (i / EH) * EH;
        const float* xp = s + ((size_t)b * Tv + (Tv - 1)) * PTc;
        float gv[4];
        #pragma unroll
        for (int g = 0; g < 4; g++) {
            float a = ebB[g * EH + j];
            #pragma unroll
            for (int k = 0; k < 5; k++) a += eWihB[(size_t)(g * EH + j) * PTc + k] * xp[k];
            gv[g] = a;
        }
        float c = sigf(gv[0]) * tanh_f(gv[2]);     // f-gate * 0 dropped
        d_hback[i] = sigf(gv[3]) * tanh_f(c);
    }
}

__global__ void __launch_bounds__(NTHR, 1) enc_kernel(const float* __restrict__ s) {
    __shared__ float As[16][68];
    __shared__ float Bs[16][132];
    int bid = blockIdx.x;
    for (int t = 0; t < Tv; t++) {
        const float* hprev = d_hE[t & 1];
        float* hnext = d_hE[(t + 1) & 1];
        for (int u = bid; u < 128; u += NBLK) {   // 16 row-tiles x 8 col-tiles
            int tm = u >> 3, tn = u & 7;
            gate_tile_impl(hprev, d_WhhF, d_WihF, nullptr, d_bF, s, t,
                           d_cE, hnext, tm * 64, tn * 128, EH, EH, As, Bs);
        }
        grid_sync();
    }
    // final encoder h is in d_hE[0] (256 steps, even)
}

__global__ void vae1_k(const float* __restrict__ Wmu, const float* __restrict__ bmu,
                       const float* __restrict__ Wsig, const float* __restrict__ bsig,
                       const float* __restrict__ eps)
{
    __shared__ float hrow[2 * EH];
    int b = blockIdx.x;
    for (int k = threadIdx.x; k < 2 * EH; k += blockDim.x)
        hrow[k] = (k < EH) ? d_hE[0][(size_t)b * EH + k] : d_hback[(size_t)b * EH + (k - EH)];
    __syncthreads();
    int j = threadIdx.x;
    if (j < ZL) {
        float mu = bmu[j], ps = bsig[j];
        for (int k = 0; k < 2 * EH; k++) {
            float h = hrow[k];
            mu += h * Wmu[(size_t)j * (2 * EH) + k];
            ps += h * Wsig[(size_t)j * (2 * EH) + k];
        }
        d_z[(size_t)b * ZL + j] = mu + __expf(0.5f * ps) * eps[(size_t)b * ZL + j];
    }
}

__global__ void vae2_k(const float* __restrict__ Wh0, const float* __restrict__ bh0,
                       const float* __restrict__ dWih, const float* __restrict__ db)
{
    __shared__ float zr[ZL];
    int b = blockIdx.x;
    for (int k = threadIdx.x; k < ZL; k += blockDim.x) zr[k] = d_z[(size_t)b * ZL + k];
    __syncthreads();
    for (int o = threadIdx.x; o < DH + 4 * DH; o += blockDim.x) {
        if (o < DH) {
            float a = bh0[o];
            const float* wp = Wh0 + (size_t)o * ZL;
            for (int k = 0; k < ZL; k++) a += zr[k] * wp[k];
            d_hD[0][(size_t)b * DH + o] = tanh_f(a);
            d_cD[(size_t)b * DH + o] = 0.f;
        } else {
            int n = o - DH;
            int j = n >> 2, g4 = n & 3;
            int rw = g4 * DH + j;
            float a = db[rw];
            const float* wp = dWih + (size_t)rw * (PTc + ZL) + PTc;
            for (int k = 0; k < ZL; k++) a += zr[k] * wp[k];
            d_zproj[(size_t)b * (4 * DH) + n] = a;
        }
    }
}

__global__ void __launch_bounds__(NTHR, 1) dec_kernel(const float* __restrict__ s,
    const float* __restrict__ Wout, const float* __restrict__ bout, float* __restrict__ out)
{
    __shared__ float As[16][68];
    __shared__ float Bs[16][132];
    __shared__ float ys[64][124];
    __shared__ float wsum[8];
    int bid = blockIdx.x;
    for (int t = 0; t < Tv; t++) {
        const float* hprev = d_hD[t & 1];
        float* hnext = d_hD[(t + 1) & 1];
        if (t >= 2) qknorm(out, t - 2);
        int nun = 256 + ((t >= 1) ? 16 : 0);   // 256 gate tiles, 16 y tiles (for step t-1)
        for (int u = bid; u < nun; u += NBLK) {
            if (u < 256) {
                int tm = u >> 4, tn = u & 15;
                gate_tile_impl(hprev, d_WhhD, d_WihS, d_zproj, nullptr, s, t - 1,
                               d_cD, hnext, tm * 64, tn * 128, DH, DH, As, Bs);
            } else {
                y_tile(hprev, Wout, bout, out, t - 1, (u - 256) * 64, As, Bs, ys, wsum);
            }
        }
        grid_sync();
    }
    // tail: y(255) on h in buffer 0, then final qk normalizations
    qknorm(out, 254);
    for (int u = bid; u < 16; u += NBLK)
        y_tile(d_hD[0], Wout, bout, out, 255, u * 64, As, Bs, ys, wsum);
    grid_sync();
    qknorm(out, 255);
}

// ---------------- launch ----------------
extern "C" void kernel_launch(void* const* d_in, const int* in_sizes, int n_in,
                              void* d_out, int out_size)
{
    const float* s     = (const float*)d_in[0];
    const float* eps   = (const float*)d_in[1];
    const float* eWihF = (const float*)d_in[2];
    const float* eWhhF = (const float*)d_in[3];
    const float* ebF   = (const float*)d_in[4];
    const float* eWihB = (const float*)d_in[5];
    // d_in[6] = enc_Whh_b : provably unused (backward LSTM contributes only its first step)
    const float* ebB   = (const float*)d_in[7];
    const float* Wmu   = (const float*)d_in[8];
    const float* bmu   = (const float*)d_in[9];
    const float* Wsig  = (const float*)d_in[10];
    const float* bsig  = (const float*)d_in[11];
    const float* Wh0   = (const float*)d_in[12];
    const float* bh0   = (const float*)d_in[13];
    const float* dWih  = (const float*)d_in[14];
    const float* dWhh  = (const float*)d_in[15];
    const float* db    = (const float*)d_in[16];
    const float* Wout  = (const float*)d_in[17];
    const float* bout  = (const float*)d_in[18];
    float* out = (float*)d_out;

    reset_k<<<1, 1>>>();
    prep_k<<<2048, 256>>>(eWihF, eWhhF, ebF, eWihB, ebB, dWih, dWhh, s);
    enc_kernel<<<NBLK, NTHR>>>(s);
    vae1_k<<<Bv, 128>>>(Wmu, bmu, Wsig, bsig, eps);
    vae2_k<<<Bv, 256>>>(Wh0, bh0, dWih, db);
    dec_kernel<<<NBLK, NTHR>>>(s, Wout, bout, out);
}

// round 4
// speedup vs baseline: 2.9686x; 2.9686x over previous
#include <cuda_runtime.h>
#include <math.h>
#include <stdint.h>
#include <stddef.h>

#define Bv   1024
#define Tv   256
#define EH   256
#define DH   512
#define ZL   128
#define PTc  5
#define OUTC 123
#define NTHR 256

// ---------------- device scratch ----------------
__device__ float d_WhhF[4*EH*EH];     // encoder recurrent, gate-interleaved, tf32-rounded
__device__ float d_WihF[4*EH*PTc];    // encoder stroke input, interleaved (fp32 exact)
__device__ float d_bF[4*EH];          // encoder bias, interleaved
__device__ float d_WhhD[4*DH*DH];     // decoder recurrent, interleaved, tf32-rounded
__device__ float d_WihS[4*DH*PTc];    // decoder stroke input, interleaved (fp32 exact)
__device__ float d_WihZ[4*DH*ZL];     // decoder z input, interleaved, tf32-rounded
__device__ float d_bDi[4*DH];         // decoder bias, interleaved
__device__ float d_Wvae[2*ZL*2*EH];   // [mu;sig] rows, tf32-rounded
__device__ float d_bvae[2*ZL];
__device__ float d_hE[2][Bv*EH];
__device__ float d_cE[Bv*EH];
__device__ float d_hback[Bv*EH];
__device__ float d_mups[Bv*2*ZL];
__device__ float d_z[Bv*ZL];
__device__ float d_hD[2][Bv*DH];
__device__ float d_cD[Bv*DH];
__device__ float d_zproj[Bv*4*DH];
__device__ float d_qpart[Tv*16];
__device__ unsigned g_count;
__device__ volatile unsigned g_gen;

// ---------------- helpers ----------------
__device__ __forceinline__ float sigf(float x) { return 1.f / (1.f + __expf(-x)); }
__device__ __forceinline__ float tanh_f(float x) {
    float ax = fabsf(x);
    float e = __expf(2.f * ax);
    float t = 1.f - 2.f / (e + 1.f);
    return copysignf(t, x);
}
__device__ __forceinline__ float wsum32(float v) {
    #pragma unroll
    for (int o = 16; o; o >>= 1) v += __shfl_xor_sync(0xffffffffu, v, o);
    return v;
}
__device__ __forceinline__ float wmax32(float v) {
    #pragma unroll
    for (int o = 16; o; o >>= 1) v = fmaxf(v, __shfl_xor_sync(0xffffffffu, v, o));
    return v;
}
__device__ __forceinline__ float f2tf(float x) {
    unsigned r; asm("cvt.rna.tf32.f32 %0, %1;" : "=r"(r) : "f"(x));
    return __uint_as_float(r);
}
__device__ __forceinline__ void mma8(float c[4], unsigned a0, unsigned a1, unsigned a2,
                                     unsigned a3, unsigned b0, unsigned b1) {
    asm volatile(
        "mma.sync.aligned.m16n8k8.row.col.f32.tf32.tf32.f32 "
        "{%0,%1,%2,%3}, {%4,%5,%6,%7}, {%8,%9}, {%0,%1,%2,%3};"
        : "+f"(c[0]), "+f"(c[1]), "+f"(c[2]), "+f"(c[3])
        : "r"(a0), "r"(a1), "r"(a2), "r"(a3), "r"(b0), "r"(b1));
}

__device__ __forceinline__ void grid_sync() {
    __threadfence();
    __syncthreads();
    if (threadIdx.x == 0) {
        unsigned gen = g_gen;
        if (atomicAdd(&g_count, 1u) == gridDim.x - 1) {
            g_count = 0;
            __threadfence();
            g_gen = gen + 1;
        } else {
            while (g_gen == gen) { __nanosleep(64); }
        }
    }
    __syncthreads();
    __threadfence();
}

// ---------------- tf32 MMA tile: C[MT*32 x 128] += A @ B^T ----------------
// 8 warps: wm in 0..1 (MT*16 rows each), wn in 0..3 (32 cols each).
// SMEM stride 36 words -> fragment LDS conflict-free. A may split at ksplit.
template<int MT>
__device__ __forceinline__ void mma_loop(
    const float* __restrict__ A, int lda,
    const float* __restrict__ A2, int lda2, int ksplit, int K,
    const float* __restrict__ B, int ldb, int brow0, int nvalid,
    int row0, float c[MT][4][4], float* As, float* Bs)
{
    const int tid = threadIdx.x;
    const int lane = tid & 31, warp = tid >> 5;
    const int wm = warp >> 2, wn = warp & 3;
    const int g = lane >> 2, tq = lane & 3;
    const int wrow = wm * (MT * 16);
    const int kk = (tid & 7) * 4;
    const int rr0 = tid >> 3;

    float4 pa[MT], pb[4];
    #pragma unroll
    for (int r = 0; r < MT; r++) {
        int row = row0 + rr0 + r * 32;
        const float* ap = (kk < ksplit) ? (A + (size_t)row * lda + kk)
                                        : (A2 + (size_t)row * lda2 + (kk - ksplit));
        pa[r] = *(const float4*)ap;
    }
    #pragma unroll
    for (int r = 0; r < 4; r++) {
        int col = rr0 + r * 32;
        pb[r] = (col < nvalid) ? *(const float4*)(B + (size_t)(brow0 + col) * ldb + kk)
                               : make_float4(0.f, 0.f, 0.f, 0.f);
    }

    for (int kb = 0; kb < K; kb += 32) {
        #pragma unroll
        for (int r = 0; r < MT; r++)
            *(float4*)(As + (rr0 + r * 32) * 36 + kk) = pa[r];
        #pragma unroll
        for (int r = 0; r < 4; r++)
            *(float4*)(Bs + (rr0 + r * 32) * 36 + kk) = pb[r];
        __syncthreads();
        if (kb + 32 < K) {
            int gk = kb + 32 + kk;
            #pragma unroll
            for (int r = 0; r < MT; r++) {
                int row = row0 + rr0 + r * 32;
                const float* ap = (gk < ksplit) ? (A + (size_t)row * lda + gk)
                                                : (A2 + (size_t)row * lda2 + (gk - ksplit));
                pa[r] = *(const float4*)ap;
            }
            #pragma unroll
            for (int r = 0; r < 4; r++) {
                int col = rr0 + r * 32;
                pb[r] = (col < nvalid) ? *(const float4*)(B + (size_t)(brow0 + col) * ldb + gk)
                                       : make_float4(0.f, 0.f, 0.f, 0.f);
            }
        }
        const unsigned* AsU = (const unsigned*)As;
        const unsigned* BsU = (const unsigned*)Bs;
        #pragma unroll
        for (int k8 = 0; k8 < 32; k8 += 8) {
            unsigned a[MT][4];
            #pragma unroll
            for (int mi = 0; mi < MT; mi++) {
                int rb = (wrow + mi * 16 + g) * 36 + k8 + tq;
                a[mi][0] = AsU[rb];
                a[mi][1] = AsU[rb + 8 * 36];
                a[mi][2] = AsU[rb + 4];
                a[mi][3] = AsU[rb + 8 * 36 + 4];
            }
            unsigned b[4][2];
            #pragma unroll
            for (int ni = 0; ni < 4; ni++) {
                int cb = (wn * 32 + ni * 8 + g) * 36 + k8 + tq;
                b[ni][0] = BsU[cb];
                b[ni][1] = BsU[cb + 4];
            }
            #pragma unroll
            for (int mi = 0; mi < MT; mi++)
                #pragma unroll
                for (int ni = 0; ni < 4; ni++)
                    mma8(c[mi][ni], a[mi][0], a[mi][1], a[mi][2], a[mi][3], b[ni][0], b[ni][1]);
        }
        __syncthreads();
    }
}

// ---------------- fused LSTM cell epilogue ----------------
// Interleaved cols: unit u = cols 4u..4u+3 (i,f,g,o). Lane pair (lane, lane^1)
// exchanges C-fragments so each lane owns a full (row, unit) gate quadruple.
template<int MT>
__device__ __forceinline__ void cell_epilogue(
    float c[MT][4][4], int row0, int col0, int H,
    const float* __restrict__ zproj, const float* __restrict__ bias,
    const float* __restrict__ Wih5,
    const float* __restrict__ s, int xt,
    float* __restrict__ cbuf, float* __restrict__ hnext)
{
    const int tid = threadIdx.x, lane = tid & 31, warp = tid >> 5;
    const int wm = warp >> 2, wn = warp & 3;
    const int g = lane >> 2, q = lane & 3;
    const bool hi = (q & 1) != 0;
    const int N4 = 4 * H;
    #pragma unroll
    for (int mi = 0; mi < MT; mi++) {
        int row = row0 + wm * (MT * 16) + mi * 16 + g + (hi ? 8 : 0);
        float xr[5];
        if (xt < 0) { xr[0] = 0.f; xr[1] = 0.f; xr[2] = 1.f; xr[3] = 0.f; xr[4] = 0.f; }
        else {
            const float* xp = s + ((size_t)row * Tv + xt) * PTc;
            #pragma unroll
            for (int k = 0; k < 5; k++) xr[k] = xp[k];
        }
        #pragma unroll
        for (int ni = 0; ni < 4; ni++) {
            float d0 = __shfl_xor_sync(0xffffffffu, c[mi][ni][0], 1);
            float d1 = __shfl_xor_sync(0xffffffffu, c[mi][ni][1], 1);
            float d2 = __shfl_xor_sync(0xffffffffu, c[mi][ni][2], 1);
            float d3 = __shfl_xor_sync(0xffffffffu, c[mi][ni][3], 1);
            float gi, gf, gg, go;
            if (!hi) { gi = c[mi][ni][0]; gf = c[mi][ni][1]; gg = d0; go = d1; }
            else     { gi = d2;           gf = d3;           gg = c[mi][ni][2]; go = c[mi][ni][3]; }
            int u4 = col0 + wn * 32 + ni * 8 + (q >> 1) * 4;
            float4 zb = zproj ? *(const float4*)(zproj + (size_t)row * N4 + u4)
                              : *(const float4*)(bias + u4);
            gi += zb.x; gf += zb.y; gg += zb.z; go += zb.w;
            const float* w5 = Wih5 + (size_t)u4 * 5;
            #pragma unroll
            for (int k = 0; k < 5; k++) {
                gi += xr[k] * w5[k];
                gf += xr[k] * w5[5 + k];
                gg += xr[k] * w5[10 + k];
                go += xr[k] * w5[15 + k];
            }
            size_t p = (size_t)row * H + (u4 >> 2);
            float cc = sigf(gf) * cbuf[p] + sigf(gi) * tanh_f(gg);
            cbuf[p] = cc;
            hnext[p] = sigf(go) * tanh_f(cc);
        }
    }
}

// ---------------- y epilogue: stage halves to SMEM, mixture transforms ----------------
__device__ __forceinline__ void y_epilogue(
    float c[4][4][4], int row0, int tstep,
    const float* __restrict__ bout, float* __restrict__ out,
    float* ys /* 64*128 */, float* wsum)
{
    const int tid = threadIdx.x, lane = tid & 31, warp = tid >> 5;
    const int wm = warp >> 2, wn = warp & 3;
    const int g = lane >> 2, q = lane & 3;
    for (int half = 0; half < 2; half++) {
        if (wm == half) {
            #pragma unroll
            for (int mi = 0; mi < 4; mi++)
                #pragma unroll
                for (int ni = 0; ni < 4; ni++)
                    #pragma unroll
                    for (int cid = 0; cid < 4; cid++) {
                        int col = wn * 32 + ni * 8 + 2 * q + (cid & 1);
                        if (col < OUTC) {
                            int r = mi * 16 + g + ((cid >= 2) ? 8 : 0);
                            ys[r * 128 + col] = c[mi][ni][cid] + bout[col];
                        }
                    }
        }
        __syncthreads();
        float qacc = 0.f;
        for (int rr = 0; rr < 8; rr++) {
            int r = warp * 8 + rr;
            int brow = row0 + half * 64 + r;
            float* orow = out + ((size_t)tstep * Bv + brow) * OUTC;
            float v = (lane < 20) ? ys[r * 128 + lane * 6] : -3.0e38f;
            float m = wmax32(v);
            float e = (lane < 20) ? __expf(v - m) : 0.f;
            float ss = wsum32(e);
            if (lane < 20) {
                orow[lane]       = e / ss;
                orow[20 + lane]  = ys[r * 128 + lane * 6 + 1];
                orow[40 + lane]  = ys[r * 128 + lane * 6 + 2];
                orow[60 + lane]  = __expf(ys[r * 128 + lane * 6 + 3]);
                orow[80 + lane]  = __expf(ys[r * 128 + lane * 6 + 4]);
                orow[100 + lane] = tanh_f(ys[r * 128 + lane * 6 + 5]);
            } else if (lane < 23) {
                float eq = __expf(ys[r * 128 + 120 + lane - 20]);
                orow[120 + lane - 20] = eq;   // normalized later by qknorm
                qacc += eq;
            }
        }
        float qs = wsum32(qacc);
        if (lane == 0) wsum[warp] = qs;
        __syncthreads();
        if (tid == 0) {
            float tot = 0.f;
            #pragma unroll
            for (int i = 0; i < 8; i++) tot += wsum[i];
            d_qpart[tstep * 16 + ((row0 + half * 64) >> 6)] = tot;
        }
        __syncthreads();
    }
}

__device__ __forceinline__ void qknorm(float* __restrict__ out, int t) {
    float tot = 0.f;
    #pragma unroll
    for (int i = 0; i < 16; i++) tot += d_qpart[t * 16 + i];
    float inv = 1.f / tot;
    for (int idx = blockIdx.x * NTHR + threadIdx.x; idx < Bv * 3; idx += gridDim.x * NTHR)
        out[((size_t)t * Bv + (idx / 3)) * OUTC + 120 + (idx % 3)] *= inv;
}

// ---------------- kernels ----------------
__global__ void reset_k() { g_count = 0; g_gen = 0; }

__global__ void prep_k(const float* __restrict__ eWihF, const float* __restrict__ eWhhF,
                       const float* __restrict__ ebF,  const float* __restrict__ eWihB,
                       const float* __restrict__ ebB,  const float* __restrict__ dWih,
                       const float* __restrict__ dWhh, const float* __restrict__ db,
                       const float* __restrict__ Wmu,  const float* __restrict__ bmu,
                       const float* __restrict__ Wsig, const float* __restrict__ bsig,
                       const float* __restrict__ s)
{
    int gt = blockIdx.x * blockDim.x + threadIdx.x;
    int gs = gridDim.x * blockDim.x;
    for (int i = gt; i < 4 * DH * DH; i += gs) {
        int n = i / DH, k = i - n * DH, j = n >> 2, g4 = n & 3;
        d_WhhD[i] = f2tf(dWhh[(size_t)(g4 * DH + j) * DH + k]);
    }
    for (int i = gt; i < 4 * DH * PTc; i += gs) {
        int n = i / PTc, k = i - n * PTc, j = n >> 2, g4 = n & 3;
        d_WihS[i] = dWih[(size_t)(g4 * DH + j) * (PTc + ZL) + k];
    }
    for (int i = gt; i < 4 * DH * ZL; i += gs) {
        int n = i / ZL, k = i - n * ZL, j = n >> 2, g4 = n & 3;
        d_WihZ[i] = f2tf(dWih[(size_t)(g4 * DH + j) * (PTc + ZL) + PTc + k]);
    }
    for (int i = gt; i < 4 * DH; i += gs) {
        int j = i >> 2, g4 = i & 3;
        d_bDi[i] = db[g4 * DH + j];
    }
    for (int i = gt; i < 4 * EH * EH; i += gs) {
        int n = i / EH, k = i - n * EH, j = n >> 2, g4 = n & 3;
        d_WhhF[i] = f2tf(eWhhF[(size_t)(g4 * EH + j) * EH + k]);
    }
    for (int i = gt; i < 4 * EH * PTc; i += gs) {
        int n = i / PTc, k = i - n * PTc, j = n >> 2, g4 = n & 3;
        d_WihF[i] = eWihF[(g4 * EH + j) * PTc + k];
    }
    for (int i = gt; i < 4 * EH; i += gs) {
        int j = i >> 2, g4 = i & 3;
        d_bF[i] = ebF[g4 * EH + j];
    }
    for (int i = gt; i < 2 * ZL * 2 * EH; i += gs) {
        int j = i / (2 * EH), k = i - j * (2 * EH);
        d_Wvae[i] = f2tf((j < ZL) ? Wmu[(size_t)j * (2 * EH) + k]
                                  : Wsig[(size_t)(j - ZL) * (2 * EH) + k]);
    }
    for (int i = gt; i < 2 * ZL; i += gs)
        d_bvae[i] = (i < ZL) ? bmu[i] : bsig[i - ZL];
    for (int i = gt; i < Bv * EH; i += gs) { d_hE[0][i] = 0.f; d_cE[i] = 0.f; }
    // backward encoder LSTM collapses to a single step (zero state, input x[T-1])
    for (int i = gt; i < Bv * EH; i += gs) {
        int b = i / EH, j = i - (i / EH) * EH;
        const float* xp = s + ((size_t)b * Tv + (Tv - 1)) * PTc;
        float gv[4];
        #pragma unroll
        for (int g = 0; g < 4; g++) {
            float a = ebB[g * EH + j];
            #pragma unroll
            for (int k = 0; k < 5; k++) a += eWihB[(size_t)(g * EH + j) * PTc + k] * xp[k];
            gv[g] = a;
        }
        float c = sigf(gv[0]) * tanh_f(gv[2]);
        d_hback[i] = sigf(gv[3]) * tanh_f(c);
    }
}

__global__ void __launch_bounds__(NTHR, 1) enc_kernel(const float* __restrict__ s) {
    __shared__ __align__(16) float sbuf[9216];
    float* As = sbuf; float* Bs = sbuf + 4608;
    int bid = blockIdx.x;                 // 128 blocks: 16 row-tiles(64) x 8 col-tiles(128)
    int row0 = (bid >> 3) * 64, col0 = (bid & 7) * 128;
    for (int t = 0; t < Tv; t++) {
        const float* hprev = d_hE[t & 1];
        float* hnext = d_hE[(t + 1) & 1];
        float c[2][4][4] = {};
        mma_loop<2>(hprev, EH, hprev, EH, EH, EH, d_WhhF, EH, col0, 128, row0, c, As, Bs);
        cell_epilogue<2>(c, row0, col0, EH, nullptr, d_bF, d_WihF, s, t, d_cE, hnext);
        grid_sync();
    }
}

__global__ void __launch_bounds__(NTHR, 1) vae1_mma() {
    __shared__ __align__(16) float sbuf[9216];
    float* As = sbuf; float* Bs = sbuf + 4608;
    int row0 = (blockIdx.x >> 1) * 128, col0 = (blockIdx.x & 1) * 128;
    float c[4][4][4] = {};
    mma_loop<4>(d_hE[0], EH, d_hback, EH, EH, 2 * EH, d_Wvae, 2 * EH, col0, 128, row0, c, As, Bs);
    const int lane = threadIdx.x & 31, warp = threadIdx.x >> 5;
    const int wm = warp >> 2, wn = warp & 3, g = lane >> 2, q = lane & 3;
    #pragma unroll
    for (int mi = 0; mi < 4; mi++)
        #pragma unroll
        for (int ni = 0; ni < 4; ni++)
            #pragma unroll
            for (int cid = 0; cid < 4; cid++) {
                int row = row0 + wm * 64 + mi * 16 + g + ((cid >= 2) ? 8 : 0);
                int col = col0 + wn * 32 + ni * 8 + 2 * q + (cid & 1);
                d_mups[(size_t)row * (2 * ZL) + col] = c[mi][ni][cid] + d_bvae[col];
            }
}

__global__ void zk(const float* __restrict__ eps) {
    int i = blockIdx.x * blockDim.x + threadIdx.x;
    if (i < Bv * ZL) {
        int b = i >> 7, j = i & 127;
        float mu = d_mups[(size_t)b * (2 * ZL) + j];
        float ps = d_mups[(size_t)b * (2 * ZL) + ZL + j];
        d_z[i] = mu + __expf(0.5f * ps) * eps[i];
    }
}

__global__ void __launch_bounds__(NTHR, 1) vae2_mma(const float* __restrict__ Wh0,
                                                    const float* __restrict__ bh0) {
    __shared__ __align__(16) float sbuf[9216];
    float* As = sbuf; float* Bs = sbuf + 4608;
    const int lane = threadIdx.x & 31, warp = threadIdx.x >> 5;
    const int wm = warp >> 2, wn = warp & 3, g = lane >> 2, q = lane & 3;
    float c[4][4][4] = {};
    if (blockIdx.x < 32) {     // h0 = tanh(z @ Wh0^T + bh0) : [1024 x 512]
        int row0 = (blockIdx.x >> 2) * 128, col0 = (blockIdx.x & 3) * 128;
        mma_loop<4>(d_z, ZL, d_z, ZL, ZL, ZL, Wh0, ZL, col0, 128, row0, c, As, Bs);
        #pragma unroll
        for (int mi = 0; mi < 4; mi++)
            #pragma unroll
            for (int ni = 0; ni < 4; ni++)
                #pragma unroll
                for (int cid = 0; cid < 4; cid++) {
                    int row = row0 + wm * 64 + mi * 16 + g + ((cid >= 2) ? 8 : 0);
                    int col = col0 + wn * 32 + ni * 8 + 2 * q + (cid & 1);
                    size_t p = (size_t)row * DH + col;
                    d_hD[0][p] = tanh_f(c[mi][ni][cid] + bh0[col]);
                    d_cD[p] = 0.f;
                }
    } else {                   // zproj = z @ WihZ^T + bDi : [1024 x 2048] interleaved
        int u = blockIdx.x - 32;
        int row0 = (u >> 4) * 128, col0 = (u & 15) * 128;
        mma_loop<4>(d_z, ZL, d_z, ZL, ZL, ZL, d_WihZ, ZL, col0, 128, row0, c, As, Bs);
        #pragma unroll
        for (int mi = 0; mi < 4; mi++)
            #pragma unroll
            for (int ni = 0; ni < 4; ni++)
                #pragma unroll
                for (int cid = 0; cid < 4; cid++) {
                    int row = row0 + wm * 64 + mi * 16 + g + ((cid >= 2) ? 8 : 0);
                    int col = col0 + wn * 32 + ni * 8 + 2 * q + (cid & 1);
                    d_zproj[(size_t)row * (4 * DH) + col] = c[mi][ni][cid] + d_bDi[col];
                }
    }
}

__global__ void __launch_bounds__(NTHR, 1) dec_kernel(const float* __restrict__ s,
    const float* __restrict__ Wout, const float* __restrict__ bout, float* __restrict__ out)
{
    __shared__ __align__(16) float sbuf[9216];
    __shared__ float wsum[8];
    float* As = sbuf; float* Bs = sbuf + 4608;
    int bid = blockIdx.x;   // 136 blocks: 128 gate tiles (8x16), 8 y tiles
    for (int t = 0; t < Tv; t++) {
        const float* hprev = d_hD[t & 1];
        float* hnext = d_hD[(t + 1) & 1];
        if (t >= 2) qknorm(out, t - 2);
        if (bid < 128) {
            int row0 = (bid >> 4) * 128, col0 = (bid & 15) * 128;
            float c[4][4][4] = {};
            mma_loop<4>(hprev, DH, hprev, DH, DH, DH, d_WhhD, DH, col0, 128, row0, c, As, Bs);
            cell_epilogue<4>(c, row0, col0, DH, d_zproj, nullptr, d_WihS, s, t - 1, d_cD, hnext);
        } else if (t >= 1) {
            int row0 = (bid - 128) * 128;
            float c[4][4][4] = {};
            mma_loop<4>(hprev, DH, hprev, DH, DH, DH, Wout, DH, 0, OUTC, row0, c, As, Bs);
            y_epilogue(c, row0, t - 1, bout, out, sbuf, wsum);
        }
        grid_sync();
    }
    qknorm(out, 254);
    if (bid < 8) {
        float c[4][4][4] = {};
        mma_loop<4>(d_hD[0], DH, d_hD[0], DH, DH, DH, Wout, DH, 0, OUTC, bid * 128, c, As, Bs);
        y_epilogue(c, bid * 128, 255, bout, out, sbuf, wsum);
    }
    grid_sync();
    qknorm(out, 255);
}

// ---------------- launch ----------------
extern "C" void kernel_launch(void* const* d_in, const int* in_sizes, int n_in,
                              void* d_out, int out_size)
{
    const float* s     = (const float*)d_in[0];
    const float* eps   = (const float*)d_in[1];
    const float* eWihF = (const float*)d_in[2];
    const float* eWhhF = (const float*)d_in[3];
    const float* ebF   = (const float*)d_in[4];
    const float* eWihB = (const float*)d_in[5];
    // d_in[6] = enc_Whh_b : unused (backward LSTM output only needs its first step)
    const float* ebB   = (const float*)d_in[7];
    const float* Wmu   = (const float*)d_in[8];
    const float* bmu   = (const float*)d_in[9];
    const float* Wsig  = (const float*)d_in[10];
    const float* bsig  = (const float*)d_in[11];
    const float* Wh0   = (const float*)d_in[12];
    const float* bh0   = (const float*)d_in[13];
    const float* dWih  = (const float*)d_in[14];
    const float* dWhh  = (const float*)d_in[15];
    const float* db    = (const float*)d_in[16];
    const float* Wout  = (const float*)d_in[17];
    const float* bout  = (const float*)d_in[18];
    float* out = (float*)d_out;

    reset_k<<<1, 1>>>();
    prep_k<<<2048, 256>>>(eWihF, eWhhF, ebF, eWihB, ebB, dWih, dWhh, db,
                          Wmu, bmu, Wsig, bsig, s);
    enc_kernel<<<128, NTHR>>>(s);
    vae1_mma<<<16, NTHR>>>();
    zk<<<(Bv * ZL + 255) / 256, 256>>>(eps);
    vae2_mma<<<160, NTHR>>>(Wh0, bh0);
    dec_kernel<<<136, NTHR>>>(s, Wout, bout, out);
}